// round 16
// baseline (speedup 1.0000x reference)
#include <cuda_runtime.h>
#include <cuda_fp16.h>
#include <cstdint>

#define BB 8
#define HH 256
#define WW 256
#define HW 65536

// ==================== warp-MMA + cp.async helpers (base PTX) ====================
__device__ __forceinline__ uint32_t smem_u32(const void* p) {
    uint32_t a;
    asm("{ .reg .u64 t; cvta.to.shared.u64 t, %1; cvt.u32.u64 %0, t; }" : "=r"(a) : "l"(p));
    return a;
}
#define LDM4(r, addr)                                                              \
    asm volatile("ldmatrix.sync.aligned.m8n8.x4.shared.b16 {%0,%1,%2,%3}, [%4];"   \
        : "=r"((r)[0]), "=r"((r)[1]), "=r"((r)[2]), "=r"((r)[3]) : "r"(addr))
#define MMA(d, a, b0v, b1v)                                                        \
    asm volatile("mma.sync.aligned.m16n8k16.row.col.f32.f16.f16.f32 "              \
        "{%0,%1,%2,%3}, {%4,%5,%6,%7}, {%8,%9}, {%0,%1,%2,%3};"                    \
        : "+f"((d)[0]), "+f"((d)[1]), "+f"((d)[2]), "+f"((d)[3])                   \
        : "r"((a)[0]), "r"((a)[1]), "r"((a)[2]), "r"((a)[3]), "r"(b0v), "r"(b1v))
#define CP16(dst, src, n)                                                          \
    asm volatile("cp.async.cg.shared.global [%0], [%1], 16, %2;"                   \
        :: "r"(dst), "l"(src), "r"(n))
#define CP_COMMIT() asm volatile("cp.async.commit_group;")
#define CP_WAIT1()  asm volatile("cp.async.wait_group 1;")
#define CP_WAIT0()  asm volatile("cp.async.wait_group 0;")

// ==================== scratch ====================
__device__ __align__(128) float g_feat[(size_t)BB * 64 * HW];
__device__ __align__(128) float g_dx  [(size_t)BB * 64 * HW];
__device__ __align__(128) __half g_in  [(size_t)BB * HW * 64];    // NHWC fp16 of featmap_in
__device__ __align__(128) __half g_actv[(size_t)BB * HW * 128];   // NHWC fp16 actv
__device__ __align__(128) float g_table[BB * 9 * 35 * 128];
__device__ __align__(128) float g_codes[BB * 35 * 64];
__device__ __align__(128) float g_sums [BB * 64 * 36];
__device__ __align__(128) float g_cnt  [BB * 36];
__device__ __align__(128) float g_stats[2 * BB * 64];
__device__ __align__(128) __half g_w1m[9 * 128 * 64];              // [tap][oc'][ic]
__device__ __align__(128) __half g_w2m[9 * 128 * 128];             // [tap][oc'][ic 0-127]

// ==================== small kernels ====================
__global__ void k_zero() {
    int i = blockIdx.x * 256 + threadIdx.x;
    if (i < BB * 64 * 36) g_sums[i] = 0.f;
    if (i < BB * 36)      g_cnt[i]  = 0.f;
}

__global__ void k_wpack(const float* __restrict__ wc, const float* __restrict__ wc0,
                        const float* __restrict__ wg, const float* __restrict__ wb) {
    int i = blockIdx.x * 256 + threadIdx.x;
    if (i < 9 * 128 * 64) {
        int ic  = i & 63;
        int oc  = (i >> 6) & 127;
        int tap = i >> 13;
        const float* src = (oc < 64) ? wc : wc0;
        g_w1m[i] = __float2half_rn(src[((oc & 63) * 64 + ic) * 9 + tap]);
    }
    if (i < 9 * 128 * 128) {
        int ic  = i & 127;
        int ocp = (i >> 7) & 127;
        int tap = i >> 14;
        const float* src = (ocp < 64) ? wg : wb;
        g_w2m[i] = __float2half_rn(src[((ocp & 63) * 128 + ic) * 9 + tap]);
    }
}

// NCHW fp32 -> NHWC fp16 (vectorized 8B stores)
__global__ void k_split(const float* __restrict__ in) {
    __shared__ float t[64][65];
    int b = blockIdx.y;
    int p0 = blockIdx.x * 64;
    int tid = threadIdx.x;
    for (int i = tid; i < 64 * 64; i += 256) {
        int c = i >> 6, px = i & 63;
        t[c][px] = in[((size_t)(b * 64 + c)) * HW + p0 + px];
    }
    __syncthreads();
    for (int i = tid; i < 1024; i += 256) {
        int px = i >> 4, c4 = (i & 15) * 4;
        __half h0 = __float2half_rn(t[c4 + 0][px]);
        __half h1 = __float2half_rn(t[c4 + 1][px]);
        __half h2 = __float2half_rn(t[c4 + 2][px]);
        __half h3 = __float2half_rn(t[c4 + 3][px]);
        uint32_t w01 = (uint32_t)__half_as_ushort(h0) | ((uint32_t)__half_as_ushort(h1) << 16);
        uint32_t w23 = (uint32_t)__half_as_ushort(h2) | ((uint32_t)__half_as_ushort(h3) << 16);
        size_t o = (((size_t)b * HW + p0 + px) << 6) + c4;
        *(uint2*)(g_in + o) = make_uint2(w01, w23);
    }
}

// ==================== conv1 smem constants (K=64 rows, 144B stride) ====================
static constexpr int SA_TOT  = 132 * 144;              // 19008
static constexpr int SW_OFF  = SA_TOT;                 // 19008
static constexpr int WBUF    = 128 * 144;              // 18432
static constexpr int SMEM_C1 = SW_OFF + 2 * WBUF;      // 55872

// ==================== conv2 smem constants (K=128 rows, 272B stride) ====================
static constexpr int SA2     = 132 * 272;              // 35904
static constexpr int SW_OFF2 = SA2;                    // 35904
static constexpr int WBUF2   = 128 * 272;              // 34816
static constexpr int SMEM_C2 = SW_OFF2 + 2 * WBUF2;    // 105536

// k_actv smem: table 9*35*128 f32 + ns
static constexpr int SMEM_ACTV = 9 * 35 * 128 * 4 + 324 * 4;  // 162576

// ==================== conv1+conv_c0: fp16 single-term, cp.async pipelined ====================
__global__ void __launch_bounds__(128, 2)
k_conv1mma(const float* __restrict__ bc_, const float* __restrict__ bc0_) {
    extern __shared__ __align__(1024) char sm[];
    uint32_t sa = smem_u32(sm);
    int tid = threadIdx.x;
    int w = tid >> 5, l = tid & 31;
    int x0 = blockIdx.x * 128, y = blockIdx.y, b = blockIdx.z;
    int mrow = (w & 1) * 64, ncol = (w >> 1) * 64;

    auto stageW = [&](int tap, int buf) {
        const char* wg = (const char*)g_w1m + (size_t)tap * 16384;
        for (int idx = tid; idx < 1024; idx += 128) {
            int oc = idx >> 3, ch = idx & 7;
            uint32_t d = sa + SW_OFF + buf * WBUF + oc * 144 + ch * 16;
            CP16(d, wg + idx * 16, 16);
        }
        CP_COMMIT();
    };
    auto stageA = [&](int dy) {
        int iy = y + dy - 1;
        bool rowok = ((unsigned)iy < 256u);
        int iyc = rowok ? iy : 0;
        for (int idx = tid; idx < 1040; idx += 128) {
            int j = idx >> 3, ch = idx & 7;
            int x = x0 - 1 + j;
            bool ok = rowok && ((unsigned)x < 256u);
            int xc = ok ? x : 0;
            const void* gp = g_in + (((size_t)b * HW + iyc * 256 + xc) << 6) + ch * 8;
            CP16(sa + j * 144 + ch * 16, gp, ok ? 16 : 0);
        }
        CP_COMMIT();
    };

    float acc[4][8][4];
#pragma unroll
    for (int mt = 0; mt < 4; mt++)
#pragma unroll
        for (int nt = 0; nt < 8; nt++)
#pragma unroll
            for (int e = 0; e < 4; e++) acc[mt][nt][e] = 0.f;

    stageW(0, 0);
    for (int t = 0; t < 9; t++) {
        int dy = t / 3, dxk = t % 3, buf = t & 1;
        __syncthreads();
        if (dxk == 0) stageA(dy);
        if (t < 8) stageW(t + 1, (t + 1) & 1);
        if (t < 8) { CP_WAIT1(); } else { CP_WAIT0(); }
        __syncthreads();

        uint32_t aBase = sa + (mrow + dxk + (l & 15)) * 144 + (l >> 4) * 16;
        uint32_t bBase = sa + SW_OFF + buf * WBUF +
                         (ncol + ((l >> 4) << 3) + (l & 7)) * 144 + ((l >> 3) & 1) * 16;
#pragma unroll
        for (int ks = 0; ks < 4; ks++) {
            uint32_t ah[4][4];
#pragma unroll
            for (int mt = 0; mt < 4; mt++)
                LDM4(ah[mt], aBase + mt * 16 * 144 + ks * 32);
#pragma unroll
            for (int np = 0; np < 4; np++) {
                uint32_t bh[4];
                LDM4(bh, bBase + np * 16 * 144 + ks * 32);
#pragma unroll
                for (int mt = 0; mt < 4; mt++) {
                    MMA(acc[mt][np * 2 + 0], ah[mt], bh[0], bh[1]);
                    MMA(acc[mt][np * 2 + 1], ah[mt], bh[2], bh[3]);
                }
            }
        }
    }

    bool isFeat = (ncol == 0);
    float* dst = isFeat ? g_feat : g_dx;
    const float* bias = isFeat ? bc_ : bc0_;
    int g = l >> 2, tg = l & 3;
#pragma unroll
    for (int nt = 0; nt < 8; nt++) {
        int c0 = (ncol & 63) + nt * 8 + tg * 2;
        float bias0 = bias[c0], bias1 = bias[c0 + 1];
#pragma unroll
        for (int mt = 0; mt < 4; mt++) {
            int px = x0 + mrow + mt * 16 + g;
            size_t o0 = ((size_t)(b * 64 + c0)) * HW + y * 256 + px;
            float v0 = acc[mt][nt][0] + bias0;
            float v1 = acc[mt][nt][1] + bias1;
            float v2 = acc[mt][nt][2] + bias0;
            float v3 = acc[mt][nt][3] + bias1;
            if (isFeat) {
                v0 = v0 >= 0.f ? v0 : 0.2f * v0;
                v1 = v1 >= 0.f ? v1 : 0.2f * v1;
                v2 = v2 >= 0.f ? v2 : 0.2f * v2;
                v3 = v3 >= 0.f ? v3 : 0.2f * v3;
            }
            dst[o0]          = v0;
            dst[o0 + HW]     = v1;
            dst[o0 + 8]      = v2;
            dst[o0 + HW + 8] = v3;
        }
    }
}

// ==================== conv2: K=128 rows, 9 stages, fused final ====================
__global__ void __launch_bounds__(128, 2)
k_conv2mma(const float* __restrict__ bg_, const float* __restrict__ bb_,
           float* __restrict__ out) {
    extern __shared__ __align__(1024) char sm[];
    uint32_t sa = smem_u32(sm);
    int tid = threadIdx.x;
    int w = tid >> 5, l = tid & 31;
    int x0 = blockIdx.x * 128, y = blockIdx.y, b = blockIdx.z;
    int mrow = (w & 1) * 64, ncol = (w >> 1) * 64;

    auto stageW = [&](int tap, int buf) {
        const char* wg = (const char*)g_w2m + (size_t)tap * 32768;
        for (int idx = tid; idx < 2048; idx += 128) {
            int oc = idx >> 4, ch = idx & 15;
            uint32_t d = sa + SW_OFF2 + buf * WBUF2 + oc * 272 + ch * 16;
            CP16(d, wg + idx * 16, 16);
        }
        CP_COMMIT();
    };
    auto stageA = [&](int dy) {
        int iy = y + dy - 1;
        bool rowok = ((unsigned)iy < 256u);
        int iyc = rowok ? iy : 0;
        for (int idx = tid; idx < 2080; idx += 128) {
            int j = idx >> 4, ch = idx & 15;
            int x = x0 - 1 + j;
            bool ok = rowok && ((unsigned)x < 256u);
            int xc = ok ? x : 0;
            const void* gp = g_actv + (((size_t)b * HW + iyc * 256 + xc) << 7) + ch * 8;
            CP16(sa + j * 272 + ch * 16, gp, ok ? 16 : 0);
        }
        CP_COMMIT();
    };

    float acc[4][8][4];
#pragma unroll
    for (int mt = 0; mt < 4; mt++)
#pragma unroll
        for (int nt = 0; nt < 8; nt++)
#pragma unroll
            for (int e = 0; e < 4; e++) acc[mt][nt][e] = 0.f;

    stageW(0, 0);
    for (int t = 0; t < 9; t++) {
        int dy = t / 3, dxk = t % 3, buf = t & 1;
        __syncthreads();
        if (dxk == 0) stageA(dy);
        if (t < 8) stageW(t + 1, (t + 1) & 1);
        if (t < 8) { CP_WAIT1(); } else { CP_WAIT0(); }
        __syncthreads();

        uint32_t aBase = sa + (mrow + dxk + (l & 15)) * 272 + (l >> 4) * 16;
        uint32_t bBase = sa + SW_OFF2 + buf * WBUF2 +
                         (ncol + ((l >> 4) << 3) + (l & 7)) * 272 + ((l >> 3) & 1) * 16;
#pragma unroll
        for (int ks = 0; ks < 8; ks++) {
            uint32_t ah[4][4];
#pragma unroll
            for (int mt = 0; mt < 4; mt++)
                LDM4(ah[mt], aBase + mt * 16 * 272 + ks * 32);
#pragma unroll
            for (int np = 0; np < 4; np++) {
                uint32_t bh[4];
                LDM4(bh, bBase + np * 16 * 272 + ks * 32);
#pragma unroll
                for (int mt = 0; mt < 4; mt++) {
                    MMA(acc[mt][np * 2 + 0], ah[mt], bh[0], bh[1]);
                    MMA(acc[mt][np * 2 + 1], ah[mt], bh[2], bh[3]);
                }
            }
        }
    }

    // exchange acc via smem: sgb[oc'][px], oc' 0-63 = gamma, 64-127 = beta (raw)
    __syncthreads();
    float* sgb = (float*)sm;  // 64KB (fits in 105536)
    int g = l >> 2, tg = l & 3;
#pragma unroll
    for (int nt = 0; nt < 8; nt++) {
        int c0 = ncol + nt * 8 + tg * 2;
#pragma unroll
        for (int mt = 0; mt < 4; mt++) {
            int pxl = mrow + mt * 16 + g;
            sgb[c0 * 128 + pxl]           = acc[mt][nt][0];
            sgb[(c0 + 1) * 128 + pxl]     = acc[mt][nt][1];
            sgb[c0 * 128 + pxl + 8]       = acc[mt][nt][2];
            sgb[(c0 + 1) * 128 + pxl + 8] = acc[mt][nt][3];
        }
    }
    __syncthreads();

    // fused final: out = lrelu( (dx-mu)*rstd*(1+gamma+bg) + beta+bb )
    for (int r = tid; r < 2048; r += 128) {
        int c = r >> 5, p4 = r & 31;
        float4 ga = *(float4*)&sgb[c * 128 + p4 * 4];
        float4 be = *(float4*)&sgb[(64 + c) * 128 + p4 * 4];
        float bgv = bg_[c], bbv = bb_[c];
        float m = g_stats[b * 64 + c], rs = g_stats[512 + b * 64 + c];
        size_t off = ((size_t)(b * 64 + c)) * HW + y * 256 + x0 + p4 * 4;
        float4 dx = *(const float4*)(g_dx + off);
        float4 o;
        float v;
        v = (dx.x - m) * rs * (1.f + ga.x + bgv) + be.x + bbv; o.x = v >= 0.f ? v : 0.2f * v;
        v = (dx.y - m) * rs * (1.f + ga.y + bgv) + be.y + bbv; o.y = v >= 0.f ? v : 0.2f * v;
        v = (dx.z - m) * rs * (1.f + ga.z + bgv) + be.z + bbv; o.z = v >= 0.f ? v : 0.2f * v;
        v = (dx.w - m) * rs * (1.f + ga.w + bgv) + be.w + bbv; o.w = v >= 0.f ? v : 0.2f * v;
        *(float4*)(out + off) = o;
    }
}

// ==================== instance-norm stats ====================
__global__ void k_stats() {
    int bc = blockIdx.x;
    int tid = threadIdx.x;
    const float4* p = (const float4*)(g_dx + (size_t)bc * HW);
    float s = 0.f, s2 = 0.f;
    for (int i = tid; i < HW / 4; i += 256) {
        float4 v = p[i];
        s  += v.x + v.y + v.z + v.w;
        s2 += v.x * v.x + v.y * v.y + v.z * v.z + v.w * v.w;
    }
    __shared__ float rs[256], rq[256];
    rs[tid] = s; rq[tid] = s2;
    __syncthreads();
    for (int o = 128; o > 0; o >>= 1) {
        if (tid < o) { rs[tid] += rs[tid + o]; rq[tid] += rq[tid + o]; }
        __syncthreads();
    }
    if (tid == 0) {
        float m = rs[0] * (1.f / HW);
        float var = rq[0] * (1.f / HW) - m * m;
        g_stats[bc] = m;
        g_stats[512 + bc] = rsqrtf(var + 1e-5f);
    }
}

// ==================== masked per-class mean pooling ====================
__global__ void k_pool(const int* __restrict__ seg, const float* __restrict__ bg,
                       const float* __restrict__ mask) {
    __shared__ float s_sum[64 * 36];
    __shared__ float s_cnt[36];
    int tid = threadIdx.x;
    for (int i = tid; i < 64 * 36; i += 256) s_sum[i] = 0.f;
    if (tid < 36) s_cnt[tid] = 0.f;
    __syncthreads();
    int b = blockIdx.y;
    int lane = tid & 31, cg = tid >> 5;
    int base = blockIdx.x * 4096;
    for (int p0 = 0; p0 < 4096; p0 += 32) {
        int p = base + p0 + lane;
        int s = seg[b * HW + p];
        bool q = (bg[b * HW + p] * (1.f - mask[b * HW + p])) > 0.f;
        if (q && cg == 0) atomicAdd(&s_cnt[s], 1.f);
        if (q) {
#pragma unroll
            for (int cc = 0; cc < 8; cc++) {
                int c = cg + cc * 8;
                float f = g_feat[((size_t)(b * 64 + c)) * HW + p];
                atomicAdd(&s_sum[c * 36 + s], f);
            }
        }
    }
    __syncthreads();
    for (int i = tid; i < 64 * 36; i += 256) {
        float v = s_sum[i];
        if (v != 0.f) atomicAdd(&g_sums[b * 2304 + i], v);
    }
    if (tid < 36 && s_cnt[tid] != 0.f) atomicAdd(&g_cnt[b * 36 + tid], s_cnt[tid]);
}

__global__ void k_codes() {
    int i = blockIdx.x * 256 + threadIdx.x;
    if (i >= BB * 35 * 64) return;
    int b = i / (35 * 64); int s = (i / 64) % 35; int f = i & 63;
    float cnt = g_cnt[b * 36 + s];
    bool keep = !(s >= 24 && s <= 33);
    float v = 0.f;
    if (cnt > 0.f && keep) v = g_sums[b * 2304 + f * 36 + s] / cnt;
    g_codes[i] = v;
}

__global__ void k_table(const float* __restrict__ w_sh) {
    int b = blockIdx.x / 9, k = blockIdx.x % 9;
    int o = threadIdx.x;  // 128
    __shared__ float swt[64][128];
    __shared__ float sc[64];
    for (int f = 0; f < 64; f++) swt[f][o] = w_sh[(o * 99 + f) * 9 + k];
    for (int s = 0; s < 35; s++) {
        __syncthreads();
        if (o < 64) sc[o] = g_codes[(b * 35 + s) * 64 + o];
        __syncthreads();
        float acc = w_sh[(o * 99 + 64 + s) * 9 + k];
#pragma unroll 8
        for (int f = 0; f < 64; f++)
            acc = fmaf(swt[f][o], sc[f], acc);
        g_table[((b * 9 + k) * 35 + s) * 128 + o] = acc;
    }
}

// ---------------- actv: smem-resident table, relu -> NHWC fp16 ----------------
__global__ void __launch_bounds__(256, 1)
k_actv(const int* __restrict__ seg, const float* __restrict__ bg,
       const float* __restrict__ bsh) {
    extern __shared__ __align__(16) float sact[];   // [9*35*128] table + ns after
    int* ns = (int*)(sact + 9 * 35 * 128);
    int b = blockIdx.z;
    int x0 = blockIdx.x * 16, y0 = blockIdx.y * 16;
    int tid = threadIdx.x;

    // load table for this batch into smem (40320 floats = 10080 float4)
    {
        const float4* src = (const float4*)(g_table + (size_t)b * 40320);
        float4* dst = (float4*)sact;
        for (int i = tid; i < 10080; i += 256) dst[i] = src[i];
    }
    for (int i = tid; i < 324; i += 256) {
        int r = i / 18, c = i % 18;
        int gy = y0 - 1 + r, gx = x0 - 1 + c;
        int v = -1;
        if ((unsigned)gy < 256u && (unsigned)gx < 256u) {
            int p = gy * 256 + gx;
            if (bg[b * HW + p] > 0.f) v = seg[b * HW + p];
        }
        ns[i] = v;
    }
    __syncthreads();

    int oq = tid & 31, pg = tid >> 5;
    float4 bias = ((const float4*)bsh)[oq];
    for (int pp = pg * 32; pp < pg * 32 + 32; pp++) {
        int ly = pp >> 4, lx = pp & 15;
        float4 a = bias;
#pragma unroll
        for (int ky = 0; ky < 3; ky++)
#pragma unroll
            for (int kx = 0; kx < 3; kx++) {
                int idx = ns[(ly + ky) * 18 + lx + kx];
                if (idx >= 0) {
                    float4 t = *(const float4*)&sact[(((ky * 3 + kx) * 35 + idx) << 7) + oq * 4];
                    a.x += t.x; a.y += t.y; a.z += t.z; a.w += t.w;
                }
            }
        a.x = fmaxf(a.x, 0.f); a.y = fmaxf(a.y, 0.f);
        a.z = fmaxf(a.z, 0.f); a.w = fmaxf(a.w, 0.f);
        __half h0 = __float2half_rn(a.x), h1 = __float2half_rn(a.y);
        __half h2 = __float2half_rn(a.z), h3 = __float2half_rn(a.w);
        uint32_t w01 = (uint32_t)__half_as_ushort(h0) | ((uint32_t)__half_as_ushort(h1) << 16);
        uint32_t w23 = (uint32_t)__half_as_ushort(h2) | ((uint32_t)__half_as_ushort(h3) << 16);
        int gp = (y0 + ly) * 256 + x0 + lx;
        size_t base = (((size_t)b * HW + gp) << 7) + oq * 4;
        *(uint2*)(g_actv + base) = make_uint2(w01, w23);
    }
}

// ==================== host ====================
extern "C" void kernel_launch(void* const* d_in, const int* in_sizes, int n_in,
                              void* d_out, int out_size) {
    const float* featmap_in = (const float*)d_in[0];
    const int*   seg        = (const int*)  d_in[1];
    const float* bg         = (const float*)d_in[2];
    const float* mask       = (const float*)d_in[3];
    const float* w_conv     = (const float*)d_in[4];
    const float* b_conv     = (const float*)d_in[5];
    const float* w_c0       = (const float*)d_in[6];
    const float* b_c0       = (const float*)d_in[7];
    const float* w_sh       = (const float*)d_in[8];
    const float* b_sh       = (const float*)d_in[9];
    const float* w_g        = (const float*)d_in[10];
    const float* b_g        = (const float*)d_in[11];
    const float* w_b        = (const float*)d_in[12];
    const float* b_b        = (const float*)d_in[13];

    cudaFuncSetAttribute(k_conv1mma, cudaFuncAttributeMaxDynamicSharedMemorySize, SMEM_C1);
    cudaFuncSetAttribute(k_conv2mma, cudaFuncAttributeMaxDynamicSharedMemorySize, SMEM_C2);
    cudaFuncSetAttribute(k_actv,     cudaFuncAttributeMaxDynamicSharedMemorySize, SMEM_ACTV);

    k_zero<<<72, 256>>>();
    k_wpack<<<576, 256>>>(w_conv, w_c0, w_g, w_b);
    k_split<<<dim3(1024, 8), 256>>>(featmap_in);

    // conv1 (lrelu -> g_feat) + conv_c0 (raw -> g_dx)
    k_conv1mma<<<dim3(2, 256, 8), 128, SMEM_C1>>>(b_conv, b_c0);

    k_stats<<<512, 256>>>();
    k_pool<<<dim3(16, 8), 256>>>(seg, bg, mask);
    k_codes<<<70, 256>>>();
    k_table<<<72, 128>>>(w_sh);
    k_actv<<<dim3(16, 16, 8), 256, SMEM_ACTV>>>(seg, bg, b_sh);

    // gamma/beta conv + fused instance-norm/SPADE/lrelu -> out
    k_conv2mma<<<dim3(2, 256, 8), 128, SMEM_C2>>>(b_g, b_b, (float*)d_out);
}

// round 17
// speedup vs baseline: 1.1003x; 1.1003x over previous
#include <cuda_runtime.h>
#include <cuda_fp16.h>
#include <cstdint>

#define BB 8
#define HH 256
#define WW 256
#define HW 65536

// ==================== warp-MMA + cp.async helpers (base PTX) ====================
__device__ __forceinline__ uint32_t smem_u32(const void* p) {
    uint32_t a;
    asm("{ .reg .u64 t; cvta.to.shared.u64 t, %1; cvt.u32.u64 %0, t; }" : "=r"(a) : "l"(p));
    return a;
}
#define LDM4(r, addr)                                                              \
    asm volatile("ldmatrix.sync.aligned.m8n8.x4.shared.b16 {%0,%1,%2,%3}, [%4];"   \
        : "=r"((r)[0]), "=r"((r)[1]), "=r"((r)[2]), "=r"((r)[3]) : "r"(addr))
#define MMA(d, a, b0v, b1v)                                                        \
    asm volatile("mma.sync.aligned.m16n8k16.row.col.f32.f16.f16.f32 "              \
        "{%0,%1,%2,%3}, {%4,%5,%6,%7}, {%8,%9}, {%0,%1,%2,%3};"                    \
        : "+f"((d)[0]), "+f"((d)[1]), "+f"((d)[2]), "+f"((d)[3])                   \
        : "r"((a)[0]), "r"((a)[1]), "r"((a)[2]), "r"((a)[3]), "r"(b0v), "r"(b1v))
#define CP16(dst, src, n)                                                          \
    asm volatile("cp.async.cg.shared.global [%0], [%1], 16, %2;"                   \
        :: "r"(dst), "l"(src), "r"(n))
#define CP_COMMIT() asm volatile("cp.async.commit_group;")
#define CP_WAIT1()  asm volatile("cp.async.wait_group 1;")
#define CP_WAIT0()  asm volatile("cp.async.wait_group 0;")

// ==================== scratch ====================
__device__ __align__(128) float g_feat[(size_t)BB * 64 * HW];
__device__ __align__(128) float g_dx  [(size_t)BB * 64 * HW];
__device__ __align__(128) __half g_in  [(size_t)BB * HW * 64];    // NHWC fp16 of featmap_in
__device__ __align__(128) __half g_actv[(size_t)BB * HW * 128];   // NHWC fp16 actv
__device__ __align__(128) float g_table[BB * 9 * 35 * 128];
__device__ __align__(128) float g_codes[BB * 35 * 64];
__device__ __align__(128) float g_sums [BB * 64 * 36];
__device__ __align__(128) float g_cnt  [BB * 36];
__device__ __align__(128) float g_stats[2 * BB * 64];
__device__ __align__(128) float g_sacc [2 * BB * 64];              // fused stats accum (sum, sumsq)
__device__ __align__(128) __half g_w1m[9 * 128 * 64];              // [tap][oc'][ic]
__device__ __align__(128) __half g_w2m[9 * 128 * 128];             // [tap][oc'][ic 0-127]

// ==================== small kernels ====================
__global__ void k_zero() {
    int i = blockIdx.x * 256 + threadIdx.x;
    if (i < BB * 64 * 36) g_sums[i] = 0.f;
    if (i < BB * 36)      g_cnt[i]  = 0.f;
    if (i < 2 * BB * 64)  g_sacc[i] = 0.f;
}

__global__ void k_wpack(const float* __restrict__ wc, const float* __restrict__ wc0,
                        const float* __restrict__ wg, const float* __restrict__ wb) {
    int i = blockIdx.x * 256 + threadIdx.x;
    if (i < 9 * 128 * 64) {
        int ic  = i & 63;
        int oc  = (i >> 6) & 127;
        int tap = i >> 13;
        const float* src = (oc < 64) ? wc : wc0;
        g_w1m[i] = __float2half_rn(src[((oc & 63) * 64 + ic) * 9 + tap]);
    }
    if (i < 9 * 128 * 128) {
        int ic  = i & 127;
        int ocp = (i >> 7) & 127;
        int tap = i >> 14;
        const float* src = (ocp < 64) ? wg : wb;
        g_w2m[i] = __float2half_rn(src[((ocp & 63) * 128 + ic) * 9 + tap]);
    }
}

// NCHW fp32 -> NHWC fp16 (vectorized 8B stores)
__global__ void k_split(const float* __restrict__ in) {
    __shared__ float t[64][65];
    int b = blockIdx.y;
    int p0 = blockIdx.x * 64;
    int tid = threadIdx.x;
    for (int i = tid; i < 64 * 64; i += 256) {
        int c = i >> 6, px = i & 63;
        t[c][px] = in[((size_t)(b * 64 + c)) * HW + p0 + px];
    }
    __syncthreads();
    for (int i = tid; i < 1024; i += 256) {
        int px = i >> 4, c4 = (i & 15) * 4;
        __half h0 = __float2half_rn(t[c4 + 0][px]);
        __half h1 = __float2half_rn(t[c4 + 1][px]);
        __half h2 = __float2half_rn(t[c4 + 2][px]);
        __half h3 = __float2half_rn(t[c4 + 3][px]);
        uint32_t w01 = (uint32_t)__half_as_ushort(h0) | ((uint32_t)__half_as_ushort(h1) << 16);
        uint32_t w23 = (uint32_t)__half_as_ushort(h2) | ((uint32_t)__half_as_ushort(h3) << 16);
        size_t o = (((size_t)b * HW + p0 + px) << 6) + c4;
        *(uint2*)(g_in + o) = make_uint2(w01, w23);
    }
}

// ==================== conv1 smem constants (K=64 rows, 144B stride) ====================
static constexpr int SA_TOT  = 132 * 144;              // 19008
static constexpr int SW_OFF  = SA_TOT;                 // 19008
static constexpr int WBUF    = 128 * 144;              // 18432
static constexpr int SMEM_C1 = SW_OFF + 2 * WBUF;      // 55872

// ==================== conv2 smem constants (K=128 rows, 272B stride) ====================
static constexpr int SA2     = 132 * 272;              // 35904
static constexpr int SW_OFF2 = SA2;                    // 35904
static constexpr int WBUF2   = 128 * 272;              // 34816
static constexpr int SMEM_C2 = SW_OFF2 + 2 * WBUF2;    // 105536

// ==================== conv1+conv_c0: fp16 single-term, fused stats accum ====================
__global__ void __launch_bounds__(128, 2)
k_conv1mma(const float* __restrict__ bc_, const float* __restrict__ bc0_) {
    extern __shared__ __align__(1024) char sm[];
    uint32_t sa = smem_u32(sm);
    int tid = threadIdx.x;
    int w = tid >> 5, l = tid & 31;
    int x0 = blockIdx.x * 128, y = blockIdx.y, b = blockIdx.z;
    int mrow = (w & 1) * 64, ncol = (w >> 1) * 64;

    auto stageW = [&](int tap, int buf) {
        const char* wg = (const char*)g_w1m + (size_t)tap * 16384;
        for (int idx = tid; idx < 1024; idx += 128) {
            int oc = idx >> 3, ch = idx & 7;
            uint32_t d = sa + SW_OFF + buf * WBUF + oc * 144 + ch * 16;
            CP16(d, wg + idx * 16, 16);
        }
        CP_COMMIT();
    };
    auto stageA = [&](int dy) {
        int iy = y + dy - 1;
        bool rowok = ((unsigned)iy < 256u);
        int iyc = rowok ? iy : 0;
        for (int idx = tid; idx < 1040; idx += 128) {
            int j = idx >> 3, ch = idx & 7;
            int x = x0 - 1 + j;
            bool ok = rowok && ((unsigned)x < 256u);
            int xc = ok ? x : 0;
            const void* gp = g_in + (((size_t)b * HW + iyc * 256 + xc) << 6) + ch * 8;
            CP16(sa + j * 144 + ch * 16, gp, ok ? 16 : 0);
        }
        CP_COMMIT();
    };

    float acc[4][8][4];
#pragma unroll
    for (int mt = 0; mt < 4; mt++)
#pragma unroll
        for (int nt = 0; nt < 8; nt++)
#pragma unroll
            for (int e = 0; e < 4; e++) acc[mt][nt][e] = 0.f;

    stageW(0, 0);
    for (int t = 0; t < 9; t++) {
        int dy = t / 3, dxk = t % 3, buf = t & 1;
        __syncthreads();
        if (dxk == 0) stageA(dy);
        if (t < 8) stageW(t + 1, (t + 1) & 1);
        if (t < 8) { CP_WAIT1(); } else { CP_WAIT0(); }
        __syncthreads();

        uint32_t aBase = sa + (mrow + dxk + (l & 15)) * 144 + (l >> 4) * 16;
        uint32_t bBase = sa + SW_OFF + buf * WBUF +
                         (ncol + ((l >> 4) << 3) + (l & 7)) * 144 + ((l >> 3) & 1) * 16;
#pragma unroll
        for (int ks = 0; ks < 4; ks++) {
            uint32_t ah[4][4];
#pragma unroll
            for (int mt = 0; mt < 4; mt++)
                LDM4(ah[mt], aBase + mt * 16 * 144 + ks * 32);
#pragma unroll
            for (int np = 0; np < 4; np++) {
                uint32_t bh[4];
                LDM4(bh, bBase + np * 16 * 144 + ks * 32);
#pragma unroll
                for (int mt = 0; mt < 4; mt++) {
                    MMA(acc[mt][np * 2 + 0], ah[mt], bh[0], bh[1]);
                    MMA(acc[mt][np * 2 + 1], ah[mt], bh[2], bh[3]);
                }
            }
        }
    }

    bool isFeat = (ncol == 0);
    float* dst = isFeat ? g_feat : g_dx;
    const float* bias = isFeat ? bc_ : bc0_;
    int g = l >> 2, tg = l & 3;
#pragma unroll
    for (int nt = 0; nt < 8; nt++) {
        int c0 = (ncol & 63) + nt * 8 + tg * 2;
        float bias0 = bias[c0], bias1 = bias[c0 + 1];
        float s0 = 0.f, q0 = 0.f, s1 = 0.f, q1 = 0.f;
#pragma unroll
        for (int mt = 0; mt < 4; mt++) {
            int px = x0 + mrow + mt * 16 + g;
            size_t o0 = ((size_t)(b * 64 + c0)) * HW + y * 256 + px;
            float v0 = acc[mt][nt][0] + bias0;
            float v1 = acc[mt][nt][1] + bias1;
            float v2 = acc[mt][nt][2] + bias0;
            float v3 = acc[mt][nt][3] + bias1;
            if (isFeat) {
                v0 = v0 >= 0.f ? v0 : 0.2f * v0;
                v1 = v1 >= 0.f ? v1 : 0.2f * v1;
                v2 = v2 >= 0.f ? v2 : 0.2f * v2;
                v3 = v3 >= 0.f ? v3 : 0.2f * v3;
            } else {
                s0 += v0 + v2; q0 += v0 * v0 + v2 * v2;
                s1 += v1 + v3; q1 += v1 * v1 + v3 * v3;
            }
            dst[o0]          = v0;
            dst[o0 + HW]     = v1;
            dst[o0 + 8]      = v2;
            dst[o0 + HW + 8] = v3;
        }
        if (!isFeat) {
            // reduce across the 8 g-lanes (xor masks 4, 8, 16 keep tg fixed)
#pragma unroll
            for (int off = 4; off <= 16; off <<= 1) {
                s0 += __shfl_xor_sync(0xffffffffu, s0, off);
                q0 += __shfl_xor_sync(0xffffffffu, q0, off);
                s1 += __shfl_xor_sync(0xffffffffu, s1, off);
                q1 += __shfl_xor_sync(0xffffffffu, q1, off);
            }
            if (g == 0) {
                atomicAdd(&g_sacc[b * 64 + c0], s0);
                atomicAdd(&g_sacc[512 + b * 64 + c0], q0);
                atomicAdd(&g_sacc[b * 64 + c0 + 1], s1);
                atomicAdd(&g_sacc[512 + b * 64 + c0 + 1], q1);
            }
        }
    }
}

// ==================== stats finalize ====================
__global__ void k_statfin() {
    int bc = blockIdx.x * 128 + threadIdx.x;
    if (bc >= 512) return;
    float m = g_sacc[bc] * (1.f / HW);
    float var = g_sacc[512 + bc] * (1.f / HW) - m * m;
    g_stats[bc] = m;
    g_stats[512 + bc] = rsqrtf(var + 1e-5f);
}

// ==================== conv2: K=128 rows, 9 stages, fused final ====================
__global__ void __launch_bounds__(128, 2)
k_conv2mma(const float* __restrict__ bg_, const float* __restrict__ bb_,
           float* __restrict__ out) {
    extern __shared__ __align__(1024) char sm[];
    uint32_t sa = smem_u32(sm);
    int tid = threadIdx.x;
    int w = tid >> 5, l = tid & 31;
    int x0 = blockIdx.x * 128, y = blockIdx.y, b = blockIdx.z;
    int mrow = (w & 1) * 64, ncol = (w >> 1) * 64;

    auto stageW = [&](int tap, int buf) {
        const char* wg = (const char*)g_w2m + (size_t)tap * 32768;
        for (int idx = tid; idx < 2048; idx += 128) {
            int oc = idx >> 4, ch = idx & 15;
            uint32_t d = sa + SW_OFF2 + buf * WBUF2 + oc * 272 + ch * 16;
            CP16(d, wg + idx * 16, 16);
        }
        CP_COMMIT();
    };
    auto stageA = [&](int dy) {
        int iy = y + dy - 1;
        bool rowok = ((unsigned)iy < 256u);
        int iyc = rowok ? iy : 0;
        for (int idx = tid; idx < 2080; idx += 128) {
            int j = idx >> 4, ch = idx & 15;
            int x = x0 - 1 + j;
            bool ok = rowok && ((unsigned)x < 256u);
            int xc = ok ? x : 0;
            const void* gp = g_actv + (((size_t)b * HW + iyc * 256 + xc) << 7) + ch * 8;
            CP16(sa + j * 272 + ch * 16, gp, ok ? 16 : 0);
        }
        CP_COMMIT();
    };

    float acc[4][8][4];
#pragma unroll
    for (int mt = 0; mt < 4; mt++)
#pragma unroll
        for (int nt = 0; nt < 8; nt++)
#pragma unroll
            for (int e = 0; e < 4; e++) acc[mt][nt][e] = 0.f;

    stageW(0, 0);
    for (int t = 0; t < 9; t++) {
        int dy = t / 3, dxk = t % 3, buf = t & 1;
        __syncthreads();
        if (dxk == 0) stageA(dy);
        if (t < 8) stageW(t + 1, (t + 1) & 1);
        if (t < 8) { CP_WAIT1(); } else { CP_WAIT0(); }
        __syncthreads();

        uint32_t aBase = sa + (mrow + dxk + (l & 15)) * 272 + (l >> 4) * 16;
        uint32_t bBase = sa + SW_OFF2 + buf * WBUF2 +
                         (ncol + ((l >> 4) << 3) + (l & 7)) * 272 + ((l >> 3) & 1) * 16;
#pragma unroll
        for (int ks = 0; ks < 8; ks++) {
            uint32_t ah[4][4];
#pragma unroll
            for (int mt = 0; mt < 4; mt++)
                LDM4(ah[mt], aBase + mt * 16 * 272 + ks * 32);
#pragma unroll
            for (int np = 0; np < 4; np++) {
                uint32_t bh[4];
                LDM4(bh, bBase + np * 16 * 272 + ks * 32);
#pragma unroll
                for (int mt = 0; mt < 4; mt++) {
                    MMA(acc[mt][np * 2 + 0], ah[mt], bh[0], bh[1]);
                    MMA(acc[mt][np * 2 + 1], ah[mt], bh[2], bh[3]);
                }
            }
        }
    }

    // exchange acc via smem: sgb[oc'][px], oc' 0-63 = gamma, 64-127 = beta (raw)
    __syncthreads();
    float* sgb = (float*)sm;  // 64KB (fits in 105536)
    int g = l >> 2, tg = l & 3;
#pragma unroll
    for (int nt = 0; nt < 8; nt++) {
        int c0 = ncol + nt * 8 + tg * 2;
#pragma unroll
        for (int mt = 0; mt < 4; mt++) {
            int pxl = mrow + mt * 16 + g;
            sgb[c0 * 128 + pxl]           = acc[mt][nt][0];
            sgb[(c0 + 1) * 128 + pxl]     = acc[mt][nt][1];
            sgb[c0 * 128 + pxl + 8]       = acc[mt][nt][2];
            sgb[(c0 + 1) * 128 + pxl + 8] = acc[mt][nt][3];
        }
    }
    __syncthreads();

    // fused final: out = lrelu( (dx-mu)*rstd*(1+gamma+bg) + beta+bb )
    for (int r = tid; r < 2048; r += 128) {
        int c = r >> 5, p4 = r & 31;
        float4 ga = *(float4*)&sgb[c * 128 + p4 * 4];
        float4 be = *(float4*)&sgb[(64 + c) * 128 + p4 * 4];
        float bgv = bg_[c], bbv = bb_[c];
        float m = g_stats[b * 64 + c], rs = g_stats[512 + b * 64 + c];
        size_t off = ((size_t)(b * 64 + c)) * HW + y * 256 + x0 + p4 * 4;
        float4 dx = *(const float4*)(g_dx + off);
        float4 o;
        float v;
        v = (dx.x - m) * rs * (1.f + ga.x + bgv) + be.x + bbv; o.x = v >= 0.f ? v : 0.2f * v;
        v = (dx.y - m) * rs * (1.f + ga.y + bgv) + be.y + bbv; o.y = v >= 0.f ? v : 0.2f * v;
        v = (dx.z - m) * rs * (1.f + ga.z + bgv) + be.z + bbv; o.z = v >= 0.f ? v : 0.2f * v;
        v = (dx.w - m) * rs * (1.f + ga.w + bgv) + be.w + bbv; o.w = v >= 0.f ? v : 0.2f * v;
        *(float4*)(out + off) = o;
    }
}

// ==================== masked per-class mean pooling ====================
__global__ void k_pool(const int* __restrict__ seg, const float* __restrict__ bg,
                       const float* __restrict__ mask) {
    __shared__ float s_sum[64 * 36];
    __shared__ float s_cnt[36];
    int tid = threadIdx.x;
    for (int i = tid; i < 64 * 36; i += 256) s_sum[i] = 0.f;
    if (tid < 36) s_cnt[tid] = 0.f;
    __syncthreads();
    int b = blockIdx.y;
    int lane = tid & 31, cg = tid >> 5;
    int base = blockIdx.x * 4096;
    for (int p0 = 0; p0 < 4096; p0 += 32) {
        int p = base + p0 + lane;
        int s = seg[b * HW + p];
        bool q = (bg[b * HW + p] * (1.f - mask[b * HW + p])) > 0.f;
        if (q && cg == 0) atomicAdd(&s_cnt[s], 1.f);
        if (q) {
#pragma unroll
            for (int cc = 0; cc < 8; cc++) {
                int c = cg + cc * 8;
                float f = g_feat[((size_t)(b * 64 + c)) * HW + p];
                atomicAdd(&s_sum[c * 36 + s], f);
            }
        }
    }
    __syncthreads();
    for (int i = tid; i < 64 * 36; i += 256) {
        float v = s_sum[i];
        if (v != 0.f) atomicAdd(&g_sums[b * 2304 + i], v);
    }
    if (tid < 36 && s_cnt[tid] != 0.f) atomicAdd(&g_cnt[b * 36 + tid], s_cnt[tid]);
}

__global__ void k_codes() {
    int i = blockIdx.x * 256 + threadIdx.x;
    if (i >= BB * 35 * 64) return;
    int b = i / (35 * 64); int s = (i / 64) % 35; int f = i & 63;
    float cnt = g_cnt[b * 36 + s];
    bool keep = !(s >= 24 && s <= 33);
    float v = 0.f;
    if (cnt > 0.f && keep) v = g_sums[b * 2304 + f * 36 + s] / cnt;
    g_codes[i] = v;
}

__global__ void k_table(const float* __restrict__ w_sh) {
    int b = blockIdx.x / 9, k = blockIdx.x % 9;
    int o = threadIdx.x;  // 128
    __shared__ float swt[64][128];
    __shared__ float sc[64];
    for (int f = 0; f < 64; f++) swt[f][o] = w_sh[(o * 99 + f) * 9 + k];
    for (int s = 0; s < 35; s++) {
        __syncthreads();
        if (o < 64) sc[o] = g_codes[(b * 35 + s) * 64 + o];
        __syncthreads();
        float acc = w_sh[(o * 99 + 64 + s) * 9 + k];
#pragma unroll 8
        for (int f = 0; f < 64; f++)
            acc = fmaf(swt[f][o], sc[f], acc);
        g_table[((b * 9 + k) * 35 + s) * 128 + o] = acc;
    }
}

// ---------------- actv = relu(b_sh + table conv) -> NHWC fp16 (R15 L2 version) ----------------
__global__ void k_actv(const int* __restrict__ seg, const float* __restrict__ bg,
                       const float* __restrict__ bsh) {
    __shared__ int ns[324];
    int b = blockIdx.z;
    int x0 = blockIdx.x * 16, y0 = blockIdx.y * 16;
    int tid = threadIdx.x;
    for (int i = tid; i < 324; i += 256) {
        int r = i / 18, c = i % 18;
        int gy = y0 - 1 + r, gx = x0 - 1 + c;
        int v = -1;
        if ((unsigned)gy < 256u && (unsigned)gx < 256u) {
            int p = gy * 256 + gx;
            if (bg[b * HW + p] > 0.f) v = seg[b * HW + p];
        }
        ns[i] = v;
    }
    __syncthreads();
    int oq = tid & 31, pg = tid >> 5;
    const float4* T4 = (const float4*)g_table + (size_t)b * 9 * 35 * 32;
    float4 bias = ((const float4*)bsh)[oq];
    for (int pp = pg * 32; pp < pg * 32 + 32; pp++) {
        int ly = pp >> 4, lx = pp & 15;
        float4 a = bias;
#pragma unroll
        for (int ky = 0; ky < 3; ky++)
#pragma unroll
            for (int kx = 0; kx < 3; kx++) {
                int idx = ns[(ly + ky) * 18 + lx + kx];
                if (idx >= 0) {
                    float4 t = T4[((ky * 3 + kx) * 35 + idx) * 32 + oq];
                    a.x += t.x; a.y += t.y; a.z += t.z; a.w += t.w;
                }
            }
        a.x = fmaxf(a.x, 0.f); a.y = fmaxf(a.y, 0.f);
        a.z = fmaxf(a.z, 0.f); a.w = fmaxf(a.w, 0.f);
        __half h0 = __float2half_rn(a.x), h1 = __float2half_rn(a.y);
        __half h2 = __float2half_rn(a.z), h3 = __float2half_rn(a.w);
        uint32_t w01 = (uint32_t)__half_as_ushort(h0) | ((uint32_t)__half_as_ushort(h1) << 16);
        uint32_t w23 = (uint32_t)__half_as_ushort(h2) | ((uint32_t)__half_as_ushort(h3) << 16);
        int gp = (y0 + ly) * 256 + x0 + lx;
        size_t base = (((size_t)b * HW + gp) << 7) + oq * 4;
        *(uint2*)(g_actv + base) = make_uint2(w01, w23);
    }
}

// ==================== host ====================
extern "C" void kernel_launch(void* const* d_in, const int* in_sizes, int n_in,
                              void* d_out, int out_size) {
    const float* featmap_in = (const float*)d_in[0];
    const int*   seg        = (const int*)  d_in[1];
    const float* bg         = (const float*)d_in[2];
    const float* mask       = (const float*)d_in[3];
    const float* w_conv     = (const float*)d_in[4];
    const float* b_conv     = (const float*)d_in[5];
    const float* w_c0       = (const float*)d_in[6];
    const float* b_c0       = (const float*)d_in[7];
    const float* w_sh       = (const float*)d_in[8];
    const float* b_sh       = (const float*)d_in[9];
    const float* w_g        = (const float*)d_in[10];
    const float* b_g        = (const float*)d_in[11];
    const float* w_b        = (const float*)d_in[12];
    const float* b_b        = (const float*)d_in[13];

    cudaFuncSetAttribute(k_conv1mma, cudaFuncAttributeMaxDynamicSharedMemorySize, SMEM_C1);
    cudaFuncSetAttribute(k_conv2mma, cudaFuncAttributeMaxDynamicSharedMemorySize, SMEM_C2);

    k_zero<<<72, 256>>>();
    k_wpack<<<576, 256>>>(w_conv, w_c0, w_g, w_b);
    k_split<<<dim3(1024, 8), 256>>>(featmap_in);

    // conv1 (lrelu -> g_feat) + conv_c0 (raw -> g_dx, fused stats accumulation)
    k_conv1mma<<<dim3(2, 256, 8), 128, SMEM_C1>>>(b_conv, b_c0);

    k_statfin<<<4, 128>>>();
    k_pool<<<dim3(16, 8), 256>>>(seg, bg, mask);
    k_codes<<<70, 256>>>();
    k_table<<<72, 128>>>(w_sh);
    k_actv<<<dim3(16, 16, 8), 256>>>(seg, bg, b_sh);

    // gamma/beta conv + fused instance-norm/SPADE/lrelu -> out
    k_conv2mma<<<dim3(2, 256, 8), 128, SMEM_C2>>>(b_g, b_b, (float*)d_out);
}